// round 4
// baseline (speedup 1.0000x reference)
#include <cuda_runtime.h>

// ---------------- problem constants (fixed shapes) ----------------
#define B_   4
#define D_   118
#define H_   32
#define W_   88
#define C_   80
#define NX_  360
#define NY_  360
#define XY_  (NX_ * NY_)                      // 129600
#define PPB  (D_ * H_ * W_)                   // 332,288 points per batch

#define SCR_N  ((size_t)B_ * XY_ * C_)        // 41,472,000 floats (~166 MB)

// Channel-last accumulation grid (B, X, Y, C): one point's 80 channel adds
// form a contiguous 320B run. Zero-initialized at module load; the fused
// transpose re-zeros it every launch, so every graph replay sees zeros.
__device__ float g_scratch[SCR_N];
__device__ float g_combine[B_ * 9];
__device__ float g_trans[B_ * 3];

// ---------------- kernel 0: per-batch combine = rots @ inv(intrins) --------
__global__ void setup_kernel(const float* __restrict__ rots,
                             const float* __restrict__ trans,
                             const float* __restrict__ intrins) {
    int b = threadIdx.x;
    if (b >= B_) return;
    const float* K = intrins + b * 9;
    double a00 = K[0], a01 = K[1], a02 = K[2];
    double a10 = K[3], a11 = K[4], a12 = K[5];
    double a20 = K[6], a21 = K[7], a22 = K[8];
    double det = a00 * (a11 * a22 - a12 * a21)
               - a01 * (a10 * a22 - a12 * a20)
               + a02 * (a10 * a21 - a11 * a20);
    double id = 1.0 / det;
    float inv[9];
    inv[0] = (float)(( a11 * a22 - a12 * a21) * id);
    inv[1] = (float)((-(a01 * a22 - a02 * a21)) * id);
    inv[2] = (float)(( a01 * a12 - a02 * a11) * id);
    inv[3] = (float)((-(a10 * a22 - a12 * a20)) * id);
    inv[4] = (float)(( a00 * a22 - a02 * a20) * id);
    inv[5] = (float)((-(a00 * a12 - a02 * a10)) * id);
    inv[6] = (float)(( a10 * a21 - a11 * a20) * id);
    inv[7] = (float)((-(a00 * a21 - a01 * a20)) * id);
    inv[8] = (float)(( a00 * a11 - a01 * a10) * id);
    const float* R = rots + b * 9;
    for (int i = 0; i < 3; i++)
        for (int j = 0; j < 3; j++)
            g_combine[b * 9 + i * 3 + j] =
                R[i * 3 + 0] * inv[0 * 3 + j] +
                R[i * 3 + 1] * inv[1 * 3 + j] +
                R[i * 3 + 2] * inv[2 * 3 + j];
    for (int i = 0; i < 3; i++) g_trans[b * 3 + i] = trans[b * 3 + i];
}

// 16B vector reduction to global (sm_90+): 4 channels per atomic lane-op.
__device__ __forceinline__ void red_add_v4(float* ptr, float4 v) {
    asm volatile("red.global.add.v4.f32 [%0], {%1, %2, %3, %4};"
                 :: "l"(ptr), "f"(v.x), "f"(v.y), "f"(v.z), "f"(v.w)
                 : "memory");
}

// ---------------- kernel 1: warp-per-point geometry + vector scatter -------
// One batch per launch: the 41.5MB scratch slice stays L2-resident for the
// atomics AND for the transpose that follows.
__global__ void __launch_bounds__(256)
scatter_kernel(const float* __restrict__ x, const float* __restrict__ frustum,
               int b) {
    int warp = (int)(((size_t)blockIdx.x * blockDim.x + threadIdx.x) >> 5);
    int lane = threadIdx.x & 31;
    if (warp >= PPB) return;

    // local point index within batch: ((d*H + h)*W + w)
    int p = warp;
    int w = p % W_;
    int t = p / W_;
    int h = t % H_;
    int d = t / H_;

    const float* fr = frustum + ((size_t)(d * H_ + h) * W_ + w) * 3;
    float fu = fr[0], fv = fr[1], fd = fr[2];   // uniform within warp
    float p0 = fu * fd, p1 = fv * fd, p2 = fd;

    const float* cmb = g_combine + b * 9;
    const float* tr  = g_trans   + b * 3;
    float gx = cmb[0] * p0 + cmb[1] * p1 + cmb[2] * p2 + tr[0];
    float gy = cmb[3] * p0 + cmb[4] * p1 + cmb[5] * p2 + tr[1];
    float gz = cmb[6] * p0 + cmb[7] * p1 + cmb[8] * p2 + tr[2];

    // matches ((geom - BX_LO)/DX).astype(int32) — truncation toward zero
    int cx = (int)((gx + 54.0f) / 0.3f);
    int cy = (int)((gy + 54.0f) / 0.3f);
    int cz = (int)((gz + 10.0f) / 20.0f);

    if ((unsigned)cx < (unsigned)NX_ && (unsigned)cy < (unsigned)NY_ && cz == 0) {
        size_t obase = ((size_t)(b * NX_ + cx) * NY_ + cy) * C_;   // 320B aligned
        if (lane < C_ / 4) {  // lanes 0..19: one float4 each
            const float4* xr4 =
                reinterpret_cast<const float4*>(x + ((size_t)b * PPB + p) * C_);
            float4 v = __ldcs(xr4 + lane);     // streaming: don't evict scratch
            red_add_v4(&g_scratch[obase + 4 * lane], v);
        }
    }
}

// ---------------- kernel 2: fused transpose + re-zero ----------------------
// Per batch: (XY, C) -> (C, XY), then zero the scratch tile for next replay.
// Tile: 64 q-rows x 80 channels = contiguous 20KB chunk of scratch.
__global__ void __launch_bounds__(256)
transpose_zero_kernel(float* __restrict__ out, int b) {
    __shared__ float s[64 * 81];   // [q][c], pad 81: stride mod 32 = 17 (coprime)
    int t  = threadIdx.x;
    int q0 = blockIdx.x * 64;

    float4* scr4 = reinterpret_cast<float4*>(g_scratch);
    size_t tile4 = ((size_t)b * XY_ + q0) * (C_ / 4);

    // load 1280 float4 (contiguous), scatter to smem, write zeros back
    const float4 z4 = make_float4(0.f, 0.f, 0.f, 0.f);
    #pragma unroll
    for (int k = 0; k < 5; k++) {
        int idx = t + k * 256;
        float4 v = scr4[tile4 + idx];
        int q  = idx / (C_ / 4);
        int c4 = idx % (C_ / 4);
        s[q * 81 + c4 * 4 + 0] = v.x;
        s[q * 81 + c4 * 4 + 1] = v.y;
        s[q * 81 + c4 * 4 + 2] = v.z;
        s[q * 81 + c4 * 4 + 3] = v.w;
        scr4[tile4 + idx] = z4;               // re-zero for next replay
    }
    __syncthreads();

    // write 5120 scalars: consecutive lanes -> consecutive q (coalesced),
    // smem column reads stride 81 (conflict-free)
    #pragma unroll
    for (int k = 0; k < 20; k++) {
        int o = t + k * 256;
        int c = o / 64;
        int q = o % 64;
        out[((size_t)b * C_ + c) * XY_ + q0 + q] = s[q * 81 + c];
    }
}

// ---------------- launch ----------------------------------------------------
extern "C" void kernel_launch(void* const* d_in, const int* in_sizes, int n_in,
                              void* d_out, int out_size) {
    const float* x       = (const float*)d_in[0];
    const float* rots    = (const float*)d_in[1];
    const float* trans   = (const float*)d_in[2];
    const float* intrins = (const float*)d_in[3];
    const float* frustum = (const float*)d_in[4];
    float* out = (float*)d_out;

    setup_kernel<<<1, 32>>>(rots, trans, intrins);

    // Interleave per batch so the 41.5MB scratch slice is L2-resident across
    // scatter (atomics) and transpose (reads + re-zero).
    for (int b = 0; b < B_; b++) {
        scatter_kernel<<<PPB / 8, 256>>>(x, frustum, b);        // 8 pts/block
        transpose_zero_kernel<<<XY_ / 64, 256>>>(out, b);       // 2025 blocks
    }
}

// round 5
// speedup vs baseline: 3.6218x; 3.6218x over previous
#include <cuda_runtime.h>

// ---------------- problem constants (fixed shapes) ----------------
#define B_   4
#define D_   118
#define H_   32              // == warp size: lane <-> h
#define W_   88
#define C_   80
#define NX_  360
#define NY_  360
#define XY_  (NX_ * NY_)     // 129600
#define NCOL (B_ * D_ * W_)  // 41,536 ray columns

__device__ float g_combine[B_ * 9];
__device__ float g_trans[B_ * 3];

// ---------------- kernel 0: per-batch combine = rots @ inv(intrins) --------
__global__ void setup_kernel(const float* __restrict__ rots,
                             const float* __restrict__ trans,
                             const float* __restrict__ intrins) {
    int b = threadIdx.x;
    if (b >= B_) return;
    const float* K = intrins + b * 9;
    double a00 = K[0], a01 = K[1], a02 = K[2];
    double a10 = K[3], a11 = K[4], a12 = K[5];
    double a20 = K[6], a21 = K[7], a22 = K[8];
    double det = a00 * (a11 * a22 - a12 * a21)
               - a01 * (a10 * a22 - a12 * a20)
               + a02 * (a10 * a21 - a11 * a20);
    double id = 1.0 / det;
    float inv[9];
    inv[0] = (float)(( a11 * a22 - a12 * a21) * id);
    inv[1] = (float)((-(a01 * a22 - a02 * a21)) * id);
    inv[2] = (float)(( a01 * a12 - a02 * a11) * id);
    inv[3] = (float)((-(a10 * a22 - a12 * a20)) * id);
    inv[4] = (float)(( a00 * a22 - a02 * a20) * id);
    inv[5] = (float)((-(a00 * a12 - a02 * a10)) * id);
    inv[6] = (float)(( a10 * a21 - a11 * a20) * id);
    inv[7] = (float)((-(a00 * a21 - a01 * a20)) * id);
    inv[8] = (float)(( a00 * a11 - a01 * a10) * id);
    const float* R = rots + b * 9;
    for (int i = 0; i < 3; i++)
        for (int j = 0; j < 3; j++)
            g_combine[b * 9 + i * 3 + j] =
                R[i * 3 + 0] * inv[0 * 3 + j] +
                R[i * 3 + 1] * inv[1 * 3 + j] +
                R[i * 3 + 2] * inv[2 * 3 + j];
    for (int i = 0; i < 3; i++) g_trans[b * 3 + i] = trans[b * 3 + i];
}

// ---------------- kernel 1: zero d_out (poisoned to 0xAA by harness) -------
__global__ void zero_out_kernel(float4* __restrict__ o) {
    size_t i = (size_t)blockIdx.x * blockDim.x + threadIdx.x;
    o[i] = make_float4(0.f, 0.f, 0.f, 0.f);   // grid sized exactly: no guard
}

// ---------------- kernel 2: warp-per-ray-column aggregated scatter ---------
// Structural fact: combine[0][1] == combine[1][1] == 0 exactly (K upper-
// triangular; (Ryaw@Rbase) rows 0,1 have zero middle entry; both exact in
// fp32). So gx,gy are identical for all 32 h of a (b,d,w) column; only gz
// (and thus the cz==0 test) varies with h. One warp aggregates the whole
// column in registers and commits ONE feature vector with scalar REDs
// directly into the final (B,C,X,Y) layout. A uniformity check guards the
// assumption with an exact per-h fallback.
__global__ void __launch_bounds__(256)
scatter_kernel(const float* __restrict__ x, const float* __restrict__ frustum,
               float* __restrict__ out) {
    int col  = (int)(((size_t)blockIdx.x * blockDim.x + threadIdx.x) >> 5);
    int lane = threadIdx.x & 31;                 // lane == h
    if (col >= NCOL) return;

    int w = col % W_;
    int t = col / W_;
    int d = t % D_;
    int b = t / D_;

    // frustum (D,H,W,3): [...,0]=u (w only), [...,1]=v (h only), [...,2]=d
    const float* fr = frustum + ((size_t)(d * H_ + lane) * W_ + w) * 3;
    float fu = fr[0];     // uniform across lanes
    float fv = fr[1];     // per-lane (h)
    float fd = fr[2];     // uniform across lanes
    float p0 = fu * fd, p1 = fv * fd, p2 = fd;

    const float* cmb = g_combine + b * 9;
    const float* tr  = g_trans   + b * 3;
    float gx = cmb[0] * p0 + cmb[1] * p1 + cmb[2] * p2 + tr[0];
    float gy = cmb[3] * p0 + cmb[4] * p1 + cmb[5] * p2 + tr[1];
    float gz = cmb[6] * p0 + cmb[7] * p1 + cmb[8] * p2 + tr[2];

    // matches ((geom - BX_LO)/DX).astype(int32): trunc toward zero,
    // including the (-1,0) -> 0 "kept" quirk of the reference.
    int cx = (int)((gx + 54.0f) / 0.3f);
    int cy = (int)((gy + 54.0f) / 0.3f);
    int cz = (int)((gz + 10.0f) / 20.0f);

    bool pass = (unsigned)cx < (unsigned)NX_ && (unsigned)cy < (unsigned)NY_
                && cz == 0;
    unsigned mask = __ballot_sync(0xFFFFFFFFu, pass);
    if (mask == 0u) return;                      // whole column rejected: skip x

    int src  = __ffs(mask) - 1;
    int cx0  = __shfl_sync(0xFFFFFFFFu, cx, src);
    int cy0  = __shfl_sync(0xFFFFFFFFu, cy, src);
    bool uni = __all_sync(0xFFFFFFFFu, !pass || (cx == cx0 && cy == cy0));

    size_t xbase = ((size_t)((b * D_ + d) * H_) * W_ + w) * (size_t)C_; // h=0

    if (uni) {
        // lanes 0..19: accumulate float4 of channels over passing h's
        if (lane < C_ / 4) {
            const float* xp = x + xbase + 4 * lane;
            float4 acc = make_float4(0.f, 0.f, 0.f, 0.f);
            #pragma unroll
            for (int h = 0; h < H_; h++) {
                if ((mask >> h) & 1u) {
                    float4 v = __ldcs(reinterpret_cast<const float4*>(
                        xp + (size_t)h * (W_ * C_)));
                    acc.x += v.x; acc.y += v.y; acc.z += v.z; acc.w += v.w;
                }
            }
            size_t q  = (size_t)cx0 * NY_ + cy0;
            float* op = out + ((size_t)b * C_ + 4 * lane) * XY_ + q;
            atomicAdd(op,                    acc.x);
            atomicAdd(op + (size_t)XY_,      acc.y);
            atomicAdd(op + 2 * (size_t)XY_,  acc.z);
            atomicAdd(op + 3 * (size_t)XY_,  acc.w);
        }
    } else {
        // exact fallback (never expected): per-h scalar scatter
        for (int h = 0; h < H_; h++) {
            if (!((mask >> h) & 1u)) continue;
            int cxh = __shfl_sync(0xFFFFFFFFu, cx, h);
            int cyh = __shfl_sync(0xFFFFFFFFu, cy, h);
            size_t q = (size_t)cxh * NY_ + cyh;
            const float* xr = x + xbase + (size_t)h * (W_ * C_);
            for (int c = lane; c < C_; c += 32)
                atomicAdd(out + ((size_t)b * C_ + c) * XY_ + q, xr[c]);
        }
    }
}

// ---------------- launch ----------------------------------------------------
extern "C" void kernel_launch(void* const* d_in, const int* in_sizes, int n_in,
                              void* d_out, int out_size) {
    const float* x       = (const float*)d_in[0];
    const float* rots    = (const float*)d_in[1];
    const float* trans   = (const float*)d_in[2];
    const float* intrins = (const float*)d_in[3];
    const float* frustum = (const float*)d_in[4];
    float* out = (float*)d_out;

    setup_kernel<<<1, 32>>>(rots, trans, intrins);

    // 41,472,000 floats = 10,368,000 float4 = 40500 * 256 exactly
    zero_out_kernel<<<40500, 256>>>(reinterpret_cast<float4*>(out));

    // one warp per (b,d,w) column: 41536 warps, 8 per block
    scatter_kernel<<<NCOL / 8, 256>>>(x, frustum, out);
}